// round 15
// baseline (speedup 1.0000x reference)
#include <cuda_runtime.h>

typedef unsigned long long ull;

#define B 8192
#define L 10
#define D 128
#define H 64
#define G4 256          // 4*H
#define OUT 5
#define TILE 64
#define NTHR 512
#define CSTR 68

// ------------------- global scratch -------------------
__device__ float g_xenc[(size_t)B * L * H];   // encoder hidden sequence
__device__ float g_pre[(size_t)B * L * H];    // x_enc @ W1x^T
__device__ float g_Wenc[192 * G4];            // [k][j*4+g]  k: 0..127 Wih, 128..191 Whh
__device__ float g_Wdec[69 * G4];             // [k][j*4+g]  k: 0..4 Wih, 5..68 Whh
__device__ float g_Wq[128 * H];               // [k][hh]     k: 0..63 W1h, 64..127 W1c

// ------------------- helpers -------------------
__device__ __forceinline__ ull pack2(float x, float y) {
    ull r; asm("mov.b64 %0, {%1, %2};" : "=l"(r) : "f"(x), "f"(y)); return r;
}
__device__ __forceinline__ ull dup2(float x) { return pack2(x, x); }
__device__ __forceinline__ float2 unpack2(ull v) {
    float2 f; asm("mov.b64 {%0, %1}, %2;" : "=f"(f.x), "=f"(f.y) : "l"(v)); return f;
}
__device__ __forceinline__ ull fma2(ull a, ull b, ull c) {
    ull d; asm("fma.rn.f32x2 %0, %1, %2, %3;" : "=l"(d) : "l"(a), "l"(b), "l"(c)); return d;
}
__device__ __forceinline__ float sigf(float x) {
    return __fdividef(1.f, 1.f + __expf(-x));
}
__device__ __forceinline__ float tanh_acc(float x) {
    return 1.f - __fdividef(2.f, __expf(2.f * x) + 1.f);
}
__device__ __forceinline__ float tanh_ap(float x) {
    float y; asm("tanh.approx.f32 %0, %1;" : "=f"(y) : "f"(x)); return y;
}

// =============================================================
// K0: repack weights
// =============================================================
__global__ void k_repack(const float* __restrict__ eWih, const float* __restrict__ eWhh,
                         const float* __restrict__ dWih, const float* __restrict__ dWhh,
                         const float* __restrict__ w1) {
    int idx = blockIdx.x * 256 + threadIdx.x;
    if (idx < 192 * G4) {
        int k = idx >> 8, c4 = idx & 255, j = c4 >> 2, g = c4 & 3;
        g_Wenc[idx] = (k < 128) ? eWih[(g * H + j) * D + k]
                                : eWhh[(g * H + j) * H + (k - 128)];
        return;
    }
    idx -= 192 * G4;
    if (idx < 69 * G4) {
        int k = idx >> 8, c4 = idx & 255, j = c4 >> 2, g = c4 & 3;
        g_Wdec[idx] = (k < 5) ? dWih[(g * H + j) * OUT + k]
                              : dWhh[(g * H + j) * H + (k - 5)];
        return;
    }
    idx -= 69 * G4;
    if (idx < 128 * H) {
        int k = idx >> 6, hh = idx & 63;
        g_Wq[idx] = (k < 64) ? w1[hh * 192 + k] : w1[hh * 192 + 64 + (k - 64)];
    }
}

// =============================================================
// K1: fused network, 512 threads/CTA, 64 rows/CTA.
// Encoder: Whh resident; Wih streamed. Decoder: fused A+B+E phase.
// =============================================================
__global__ __launch_bounds__(NTHR, 1) void k_net(
    const float* __restrict__ x, const float* __restrict__ h0,
    const float* __restrict__ c0, const float* __restrict__ bih,
    const float* __restrict__ bhh, const float* __restrict__ enc_attn_w,
    const float* __restrict__ w1,
    const float* __restrict__ y_hist, const float* __restrict__ h0d,
    const float* __restrict__ c0d,
    const float* __restrict__ dec_attn_b1, const float* __restrict__ dec_attn_w2,
    const float* __restrict__ dec_bih, const float* __restrict__ dec_bhh,
    const float* __restrict__ fc_w, const float* __restrict__ fc_b,
    const float* __restrict__ fcout_w, const float* __restrict__ fcout_b,
    float* __restrict__ out) {
    extern __shared__ float sm[];

    const int tid = threadIdx.x;
    const int rt = tid & 15, jc = tid >> 4;      // 16 row-threads x 32 col-threads
    const int r0 = rt * 4, j0 = jc * 2, jc8 = jc * 8;
    const int b0 = blockIdx.x * TILE;
    const int rowp = tid >> 3, dg = tid & 7;     // 64 rows x 8 d-groups

    // =========================================================
    // ENCODER (verbatim from measured-450us kernel)
    // smem: Whh_s[64][256], Bs0/Bs1[32][256], Asx[128][64], Ash[64][64], Ws1x[64][64]
    // =========================================================
    {
        float* Whh_s = sm;
        float* Bs0   = Whh_s + 64 * G4;
        float* Bs1   = Bs0 + 32 * G4;
        float* Asx   = Bs1 + 32 * G4;
        float* Ash   = Asx + 128 * 64;
        float* Ws1x  = Ash + 64 * 64;

        for (int i = tid; i < 64 * G4 / 4; i += NTHR)
            ((float4*)Whh_s)[i] = ((const float4*)(g_Wenc + 128 * G4))[i];
        for (int i = tid; i < 64 * 64; i += NTHR) {
            int e = i >> 6, hh = i & 63;
            Ws1x[e * 64 + hh] = w1[hh * 192 + 128 + e];
        }

        float4 at4[4];
        {
            float wx[L];
#pragma unroll
            for (int l = 0; l < L; l++) wx[l] = __ldg(enc_attn_w + 2 * H + l);
#pragma unroll
            for (int i = 0; i < 4; i++) at4[i] = make_float4(0.f, 0.f, 0.f, 0.f);
            const float* xp = x + (size_t)(b0 + rowp) * L * D + dg * 16;
#pragma unroll
            for (int l = 0; l < L; l++) {
#pragma unroll
                for (int i = 0; i < 4; i++) {
                    float4 v = *(const float4*)(xp + l * D + i * 4);
                    at4[i].x = fmaf(v.x, wx[l], at4[i].x);
                    at4[i].y = fmaf(v.y, wx[l], at4[i].y);
                    at4[i].z = fmaf(v.z, wx[l], at4[i].z);
                    at4[i].w = fmaf(v.w, wx[l], at4[i].w);
                }
            }
            float m = -1e30f;
#pragma unroll
            for (int i = 0; i < 4; i++)
                m = fmaxf(m, fmaxf(fmaxf(at4[i].x, at4[i].y), fmaxf(at4[i].z, at4[i].w)));
            m = fmaxf(m, __shfl_xor_sync(0xFFFFFFFFu, m, 1));
            m = fmaxf(m, __shfl_xor_sync(0xFFFFFFFFu, m, 2));
            m = fmaxf(m, __shfl_xor_sync(0xFFFFFFFFu, m, 4));
            float s = 0.f;
#pragma unroll
            for (int i = 0; i < 4; i++) {
                at4[i].x = __expf(at4[i].x - m); at4[i].y = __expf(at4[i].y - m);
                at4[i].z = __expf(at4[i].z - m); at4[i].w = __expf(at4[i].w - m);
                s += at4[i].x + at4[i].y + at4[i].z + at4[i].w;
            }
            s += __shfl_xor_sync(0xFFFFFFFFu, s, 1);
            s += __shfl_xor_sync(0xFFFFFFFFu, s, 2);
            s += __shfl_xor_sync(0xFFFFFFFFu, s, 4);
            float inv = __fdividef(1.f, s);
#pragma unroll
            for (int i = 0; i < 4; i++) {
                at4[i].x *= inv; at4[i].y *= inv; at4[i].z *= inv; at4[i].w *= inv;
            }
        }

        {
            const float* hp = h0 + (size_t)(b0 + rowp) * H + dg * 8;
            float4 v0 = *(const float4*)(hp);
            float4 v1 = *(const float4*)(hp + 4);
            int j = dg * 8;
            Ash[(j + 0) * 64 + rowp] = v0.x; Ash[(j + 1) * 64 + rowp] = v0.y;
            Ash[(j + 2) * 64 + rowp] = v0.z; Ash[(j + 3) * 64 + rowp] = v0.w;
            Ash[(j + 4) * 64 + rowp] = v1.x; Ash[(j + 5) * 64 + rowp] = v1.y;
            Ash[(j + 6) * 64 + rowp] = v1.z; Ash[(j + 7) * 64 + rowp] = v1.w;
        }
        float cr0[4], cr1[4];
        ull bp[4];
#pragma unroll
        for (int p = 0; p < 4; p++) {
            int j = j0 + (p >> 1), g0 = (p & 1) * 2;
            bp[p] = pack2(bih[g0 * H + j] + bhh[g0 * H + j],
                          bih[(g0 + 1) * H + j] + bhh[(g0 + 1) * H + j]);
        }
#pragma unroll
        for (int i = 0; i < 4; i++) {
            cr0[i] = c0[(size_t)(b0 + r0 + i) * H + j0];
            cr1[i] = c0[(size_t)(b0 + r0 + i) * H + j0 + 1];
        }
        __syncthreads();

        for (int t = 0; t < L; t++) {
            const float4* wp0 = (const float4*)g_Wenc + tid * 4;
            float4 f0 = wp0[0], f1 = wp0[1], f2 = wp0[2], f3 = wp0[3];

            {
                const float* xp = x + ((size_t)(b0 + rowp) * L + t) * D + dg * 16;
#pragma unroll
                for (int i = 0; i < 4; i++) {
                    float4 xv = *(const float4*)(xp + i * 4);
                    int k = dg * 16 + i * 4;
                    Asx[(k + 0) * 64 + rowp] = xv.x * at4[i].x;
                    Asx[(k + 1) * 64 + rowp] = xv.y * at4[i].y;
                    Asx[(k + 2) * 64 + rowp] = xv.z * at4[i].z;
                    Asx[(k + 3) * 64 + rowp] = xv.w * at4[i].w;
                }
            }
            {
                float4* b4 = (float4*)Bs0 + tid * 4;
                b4[0] = f0; b4[1] = f1; b4[2] = f2; b4[3] = f3;
            }
            __syncthreads();

            ull acc[4][4];
#pragma unroll
            for (int i = 0; i < 4; i++)
#pragma unroll
                for (int p = 0; p < 4; p++) acc[i][p] = bp[p];

            for (int kb = 0; kb < 4; kb++) {
                const float* Bsc = (kb & 1) ? Bs1 : Bs0;
                float4 n0, n1, n2, n3;
                if (kb < 3) {
                    const float4* wp = (const float4*)(g_Wenc + (kb + 1) * 32 * G4) + tid * 4;
                    n0 = wp[0]; n1 = wp[1]; n2 = wp[2]; n3 = wp[3];
                }
#pragma unroll
                for (int kk = 0; kk < 32; kk++) {
                    const float* ap = Asx + (kb * 32 + kk) * 64;
                    float4 a = *(const float4*)(ap + r0);
                    const ulonglong2* vp = (const ulonglong2*)(Bsc + kk * G4 + jc8);
                    ulonglong2 vA = vp[0], vB = vp[1];
                    float av[4] = {a.x, a.y, a.z, a.w};
#pragma unroll
                    for (int i = 0; i < 4; i++) {
                        ull ad = dup2(av[i]);
                        acc[i][0] = fma2(ad, vA.x, acc[i][0]);
                        acc[i][1] = fma2(ad, vA.y, acc[i][1]);
                        acc[i][2] = fma2(ad, vB.x, acc[i][2]);
                        acc[i][3] = fma2(ad, vB.y, acc[i][3]);
                    }
                }
                if (kb < 3) {
                    float* Bn = (kb & 1) ? Bs0 : Bs1;
                    float4* b4 = (float4*)Bn + tid * 4;
                    b4[0] = n0; b4[1] = n1; b4[2] = n2; b4[3] = n3;
                    __syncthreads();
                }
            }
#pragma unroll 8
            for (int kk = 0; kk < 64; kk++) {
                float4 a = *(const float4*)(Ash + kk * 64 + r0);
                const ulonglong2* vp = (const ulonglong2*)(Whh_s + kk * G4 + jc8);
                ulonglong2 vA = vp[0], vB = vp[1];
                float av[4] = {a.x, a.y, a.z, a.w};
#pragma unroll
                for (int i = 0; i < 4; i++) {
                    ull ad = dup2(av[i]);
                    acc[i][0] = fma2(ad, vA.x, acc[i][0]);
                    acc[i][1] = fma2(ad, vA.y, acc[i][1]);
                    acc[i][2] = fma2(ad, vB.x, acc[i][2]);
                    acc[i][3] = fma2(ad, vB.y, acc[i][3]);
                }
            }
            __syncthreads();

#pragma unroll
            for (int i = 0; i < 4; i++) {
                float2 u0 = unpack2(acc[i][0]), u1 = unpack2(acc[i][1]);
                float2 u2 = unpack2(acc[i][2]), u3 = unpack2(acc[i][3]);
                float cn0 = sigf(u0.y) * cr0[i] + sigf(u0.x) * tanh_acc(u1.x);
                float hn0 = sigf(u1.y) * tanh_acc(cn0);
                float cn1 = sigf(u2.y) * cr1[i] + sigf(u2.x) * tanh_acc(u3.x);
                float hn1 = sigf(u3.y) * tanh_acc(cn1);
                cr0[i] = cn0; cr1[i] = cn1;
                Ash[(j0) * 64 + r0 + i]     = hn0;
                Ash[(j0 + 1) * 64 + r0 + i] = hn1;
                *(float2*)(g_xenc + ((size_t)(b0 + r0 + i) * L + t) * H + j0) =
                    make_float2(hn0, hn1);
            }
            __syncthreads();

            {
                ull p0c0 = 0, p1c0 = 0, p0c1 = 0, p1c1 = 0;
#pragma unroll 8
                for (int e = 0; e < 64; e++) {
                    const float* hp = Ash + e * 64;
                    ulonglong2 hA = *(const ulonglong2*)(hp + r0);
                    float2 w = *(const float2*)(Ws1x + e * 64 + j0);
                    ull w0 = dup2(w.x), w1d = dup2(w.y);
                    p0c0 = fma2(hA.x, w0, p0c0);  p1c0 = fma2(hA.y, w0, p1c0);
                    p0c1 = fma2(hA.x, w1d, p0c1); p1c1 = fma2(hA.y, w1d, p1c1);
                }
                float2 a0 = unpack2(p0c0), a1 = unpack2(p1c0);
                float2 c0v = unpack2(p0c1), c1v = unpack2(p1c1);
                float* pb = g_pre + ((size_t)(b0 + r0) * L + t) * H + j0;
                const size_t rs = (size_t)L * H;
                *(float2*)(pb + 0 * rs) = make_float2(a0.x, c0v.x);
                *(float2*)(pb + 1 * rs) = make_float2(a0.y, c0v.y);
                *(float2*)(pb + 2 * rs) = make_float2(a1.x, c1v.x);
                *(float2*)(pb + 3 * rs) = make_float2(a1.y, c1v.y);
            }
        }
    }
    __syncthreads();   // encoder smem dead; repartition for decoder

    // =========================================================
    // DECODER PHASE — fused AB(E) + F + G, 3 syncs/step
    // =========================================================
    {
        float* Wdec  = sm;                    // [69][256]
        float* Wq    = Wdec + 69 * G4;        // [128][64]
        float* Acs   = Wq + 128 * H;          // [128][64]: 0..63 h, 64..127 c
        float* As2   = Acs + 128 * 64;        // [5][64]
        float* ctx_s = As2 + 5 * 64;          // [64][CSTR] (final step only)
        float* w2_s  = ctx_s + 64 * CSTR;     // [64]
        float* b1_s  = w2_s + 64;             // [64]
        float* fcw_s = b1_s + 64;             // [5][72]
        float* fcb_s = fcw_s + 5 * 72;        // [8]
        float* fow_s = fcb_s + 8;             // [5][128]
        float* fob_s = fow_s + 5 * 128;       // [8]

        const int rowq = tid >> 3, q8 = tid & 7;

        for (int i = tid; i < 69 * G4; i += NTHR)  Wdec[i] = g_Wdec[i];
        for (int i = tid; i < 128 * H; i += NTHR)  Wq[i]   = g_Wq[i];
        if (tid < 64) { w2_s[tid] = dec_attn_w2[tid]; b1_s[tid] = dec_attn_b1[tid]; }
        for (int i = tid; i < 5 * 69; i += NTHR) {
            int o = i / 69, k = i % 69;
            fcw_s[o * 72 + k] = fc_w[i];
        }
        for (int i = tid; i < 5 * 128; i += NTHR) fow_s[i] = fcout_w[i];
        if (tid < 5) { fcb_s[tid] = fc_b[tid]; fob_s[tid] = fcout_b[tid]; }

        {   // h0/c0 transposed (8 cols per thread)
            const float* hp = h0d + (size_t)(b0 + rowp) * H + dg * 8;
            const float* cp = c0d + (size_t)(b0 + rowp) * H + dg * 8;
            float4 h0v = *(const float4*)(hp), h1v = *(const float4*)(hp + 4);
            float4 c0v = *(const float4*)(cp), c1v = *(const float4*)(cp + 4);
            int j = dg * 8;
            Acs[(j + 0) * 64 + rowp] = h0v.x; Acs[(j + 1) * 64 + rowp] = h0v.y;
            Acs[(j + 2) * 64 + rowp] = h0v.z; Acs[(j + 3) * 64 + rowp] = h0v.w;
            Acs[(j + 4) * 64 + rowp] = h1v.x; Acs[(j + 5) * 64 + rowp] = h1v.y;
            Acs[(j + 6) * 64 + rowp] = h1v.z; Acs[(j + 7) * 64 + rowp] = h1v.w;
            Acs[(64 + j + 0) * 64 + rowp] = c0v.x; Acs[(64 + j + 1) * 64 + rowp] = c0v.y;
            Acs[(64 + j + 2) * 64 + rowp] = c0v.z; Acs[(64 + j + 3) * 64 + rowp] = c0v.w;
            Acs[(64 + j + 4) * 64 + rowp] = c1v.x; Acs[(64 + j + 5) * 64 + rowp] = c1v.y;
            Acs[(64 + j + 6) * 64 + rowp] = c1v.z; Acs[(64 + j + 7) * 64 + rowp] = c1v.w;
        }
        ull bp2[4];
#pragma unroll
        for (int p = 0; p < 4; p++) {
            int j = j0 + (p >> 1), g0 = (p & 1) * 2;
            bp2[p] = pack2(dec_bih[g0 * H + j] + dec_bhh[g0 * H + j],
                           dec_bih[(g0 + 1) * H + j] + dec_bhh[(g0 + 1) * H + j]);
        }
        __syncthreads();

        for (int t = 0; t < L; t++) {
            // ===== fused Phase AB+E: q, scores, softmax, ctx, y_tilde =====
            {
                // --- q for (rowq, hh = q8*8..+8), 4 hh-pairs ---
                ull qa[4] = {0, 0, 0, 0};
#pragma unroll 4
                for (int k = 0; k < 128; k++) {
                    ull hd = dup2(Acs[k * 64 + rowq]);
                    const ulonglong2* wp = (const ulonglong2*)(Wq + k * H + q8 * 8);
                    ulonglong2 w0 = wp[0], w1v = wp[1];
                    qa[0] = fma2(hd, w0.x, qa[0]);
                    qa[1] = fma2(hd, w0.y, qa[1]);
                    qa[2] = fma2(hd, w1v.x, qa[2]);
                    qa[3] = fma2(hd, w1v.y, qa[3]);
                }
                float qv[8];
                {
                    float2 u0 = unpack2(qa[0]), u1 = unpack2(qa[1]);
                    float2 u2 = unpack2(qa[2]), u3 = unpack2(qa[3]);
                    const float* bb = b1_s + q8 * 8;
                    qv[0] = u0.x + bb[0]; qv[1] = u0.y + bb[1];
                    qv[2] = u1.x + bb[2]; qv[3] = u1.y + bb[3];
                    qv[4] = u2.x + bb[4]; qv[5] = u2.y + bb[5];
                    qv[6] = u3.x + bb[6]; qv[7] = u3.y + bb[7];
                }
                float w2v[8];
                {
                    const float* w2p = w2_s + q8 * 8;
#pragma unroll
                    for (int i = 0; i < 8; i++) w2v[i] = w2p[i];
                }
                // --- scores + softmax ---
                const float* prep = g_pre + (size_t)(b0 + rowq) * L * H + q8 * 8;
                float at[L];
#pragma unroll
                for (int l = 0; l < L; l++) {
                    float4 p0 = *(const float4*)(prep + l * H);
                    float4 p1 = *(const float4*)(prep + l * H + 4);
                    float s;
                    s = tanh_ap(p0.x + qv[0]) * w2v[0];
                    s = fmaf(tanh_ap(p0.y + qv[1]), w2v[1], s);
                    s = fmaf(tanh_ap(p0.z + qv[2]), w2v[2], s);
                    s = fmaf(tanh_ap(p0.w + qv[3]), w2v[3], s);
                    s = fmaf(tanh_ap(p1.x + qv[4]), w2v[4], s);
                    s = fmaf(tanh_ap(p1.y + qv[5]), w2v[5], s);
                    s = fmaf(tanh_ap(p1.z + qv[6]), w2v[6], s);
                    s = fmaf(tanh_ap(p1.w + qv[7]), w2v[7], s);
                    s += __shfl_xor_sync(0xFFFFFFFFu, s, 1);
                    s += __shfl_xor_sync(0xFFFFFFFFu, s, 2);
                    s += __shfl_xor_sync(0xFFFFFFFFu, s, 4);
                    at[l] = s;
                }
                float m = at[0];
#pragma unroll
                for (int l = 1; l < L; l++) m = fmaxf(m, at[l]);
                float ssum = 0.f;
#pragma unroll
                for (int l = 0; l < L; l++) { at[l] = __expf(at[l] - m); ssum += at[l]; }
                float inv = __fdividef(1.f, ssum);
#pragma unroll
                for (int l = 0; l < L; l++) at[l] *= inv;

                // --- ctx (8 values per lane, registers) ---
                float4 c0a = make_float4(0.f, 0.f, 0.f, 0.f);
                float4 c1a = make_float4(0.f, 0.f, 0.f, 0.f);
                const float* xep = g_xenc + (size_t)(b0 + rowq) * L * H + q8 * 8;
#pragma unroll
                for (int l = 0; l < L; l++) {
                    float4 x0 = *(const float4*)(xep + l * H);
                    float4 x1 = *(const float4*)(xep + l * H + 4);
                    c0a.x = fmaf(at[l], x0.x, c0a.x); c0a.y = fmaf(at[l], x0.y, c0a.y);
                    c0a.z = fmaf(at[l], x0.z, c0a.z); c0a.w = fmaf(at[l], x0.w, c0a.w);
                    c1a.x = fmaf(at[l], x1.x, c1a.x); c1a.y = fmaf(at[l], x1.y, c1a.y);
                    c1a.z = fmaf(at[l], x1.z, c1a.z); c1a.w = fmaf(at[l], x1.w, c1a.w);
                }
                if (t == L - 1) {   // ctx only needed for the output head
                    *(float4*)(ctx_s + rowq * CSTR + q8 * 8)     = c0a;
                    *(float4*)(ctx_s + rowq * CSTR + q8 * 8 + 4) = c1a;
                }

                // --- fused Phase E: y_tilde partials + 8-lane butterfly ---
                float p[OUT];
#pragma unroll
                for (int o = 0; o < OUT; o++) {
                    const float* fw = fcw_s + o * 72 + q8 * 8;
                    float s;
                    s = c0a.x * fw[0];
                    s = fmaf(c0a.y, fw[1], s);
                    s = fmaf(c0a.z, fw[2], s);
                    s = fmaf(c0a.w, fw[3], s);
                    s = fmaf(c1a.x, fw[4], s);
                    s = fmaf(c1a.y, fw[5], s);
                    s = fmaf(c1a.z, fw[6], s);
                    s = fmaf(c1a.w, fw[7], s);
                    s += __shfl_xor_sync(0xFFFFFFFFu, s, 1);
                    s += __shfl_xor_sync(0xFFFFFFFFu, s, 2);
                    s += __shfl_xor_sync(0xFFFFFFFFu, s, 4);
                    p[o] = s;
                }
                if (q8 < OUT) {
                    int o = q8;
                    float s = p[o] + fcb_s[o];
                    const float* yh = y_hist + ((size_t)(b0 + rowq) * L + t) * OUT;
                    const float* fw = fcw_s + o * 72 + 64;
#pragma unroll
                    for (int k = 0; k < OUT; k++) s = fmaf(fw[k], yh[k], s);
                    As2[o * 64 + rowq] = s;
                }
            }
            __syncthreads();   // As2 ready; Acs reads for q done

            // ===== Phase F: gates (4 rows x 8 cols, k = 5 + 64) =====
            ull acc[4][4];
#pragma unroll
            for (int i = 0; i < 4; i++)
#pragma unroll
                for (int p = 0; p < 4; p++) acc[i][p] = bp2[p];
#pragma unroll
            for (int k = 0; k < 5; k++) {
                const float* ap = As2 + k * 64;
                float4 a = *(const float4*)(ap + r0);
                const ulonglong2* vp = (const ulonglong2*)(Wdec + k * G4 + jc8);
                ulonglong2 vA = vp[0], vB = vp[1];
                float av[4] = {a.x, a.y, a.z, a.w};
#pragma unroll
                for (int i = 0; i < 4; i++) {
                    ull ad = dup2(av[i]);
                    acc[i][0] = fma2(ad, vA.x, acc[i][0]);
                    acc[i][1] = fma2(ad, vA.y, acc[i][1]);
                    acc[i][2] = fma2(ad, vB.x, acc[i][2]);
                    acc[i][3] = fma2(ad, vB.y, acc[i][3]);
                }
            }
#pragma unroll 8
            for (int k = 0; k < 64; k++) {
                const float* ap = Acs + k * 64;
                float4 a = *(const float4*)(ap + r0);
                const ulonglong2* vp = (const ulonglong2*)(Wdec + (5 + k) * G4 + jc8);
                ulonglong2 vA = vp[0], vB = vp[1];
                float av[4] = {a.x, a.y, a.z, a.w};
#pragma unroll
                for (int i = 0; i < 4; i++) {
                    ull ad = dup2(av[i]);
                    acc[i][0] = fma2(ad, vA.x, acc[i][0]);
                    acc[i][1] = fma2(ad, vA.y, acc[i][1]);
                    acc[i][2] = fma2(ad, vB.x, acc[i][2]);
                    acc[i][3] = fma2(ad, vB.y, acc[i][3]);
                }
            }
            __syncthreads();   // old-h reads done

            // ===== Phase G: LSTM cell, update h/c (4 rows x 2 cols) =====
#pragma unroll
            for (int i = 0; i < 4; i++) {
                float2 u0 = unpack2(acc[i][0]), u1 = unpack2(acc[i][1]);
                float2 u2 = unpack2(acc[i][2]), u3 = unpack2(acc[i][3]);
                float co0 = Acs[(64 + j0) * 64 + r0 + i];
                float co1 = Acs[(64 + j0 + 1) * 64 + r0 + i];
                float cn0 = sigf(u0.y) * co0 + sigf(u0.x) * tanh_acc(u1.x);
                float hn0 = sigf(u1.y) * tanh_acc(cn0);
                float cn1 = sigf(u2.y) * co1 + sigf(u2.x) * tanh_acc(u3.x);
                float hn1 = sigf(u3.y) * tanh_acc(cn1);
                Acs[(j0) * 64 + r0 + i]          = hn0;
                Acs[(j0 + 1) * 64 + r0 + i]      = hn1;
                Acs[(64 + j0) * 64 + r0 + i]     = cn0;
                Acs[(64 + j0 + 1) * 64 + r0 + i] = cn1;
            }
            __syncthreads();
        }

        // ---- out = [h | ctx] @ fcout_w^T + fcout_b ----
        if (tid < 5 * 64) {
            int row = tid & 63, o = tid >> 6;
            float s = fob_s[o];
            const float* fw = fow_s + o * 128;
#pragma unroll 8
            for (int k = 0; k < 64; k++) s = fmaf(fw[k], Acs[k * 64 + row], s);
            const float* cx = ctx_s + row * CSTR;
#pragma unroll 8
            for (int k = 0; k < 64; k++) s = fmaf(fw[64 + k], cx[k], s);
            out[(size_t)(b0 + row) * OUT + o] = s;
        }
    }
}

// =============================================================
// launcher
// =============================================================
extern "C" void kernel_launch(void* const* d_in, const int* in_sizes, int n_in,
                              void* d_out, int out_size) {
    const float* x           = (const float*)d_in[0];
    const float* y_hist      = (const float*)d_in[1];
    const float* h0_enc      = (const float*)d_in[2];
    const float* c0_enc      = (const float*)d_in[3];
    const float* h0_dec      = (const float*)d_in[4];
    const float* c0_dec      = (const float*)d_in[5];
    const float* enc_attn_w  = (const float*)d_in[6];
    // d_in[7] enc_attn_b: softmax-shift-invariant, unused
    const float* enc_Wih     = (const float*)d_in[8];
    const float* enc_Whh     = (const float*)d_in[9];
    const float* enc_bih     = (const float*)d_in[10];
    const float* enc_bhh     = (const float*)d_in[11];
    const float* dec_attn_w1 = (const float*)d_in[12];
    const float* dec_attn_b1 = (const float*)d_in[13];
    const float* dec_attn_w2 = (const float*)d_in[14];
    // d_in[15] dec_attn_b2: softmax-shift-invariant, unused
    const float* dec_Wih     = (const float*)d_in[16];
    const float* dec_Whh     = (const float*)d_in[17];
    const float* dec_bih     = (const float*)d_in[18];
    const float* dec_bhh     = (const float*)d_in[19];
    const float* fc_w        = (const float*)d_in[20];
    const float* fc_b        = (const float*)d_in[21];
    const float* fcout_w     = (const float*)d_in[22];
    const float* fcout_b     = (const float*)d_in[23];
    float* out = (float*)d_out;

    const int enc_sm = (64 * G4 + 2 * 32 * G4 + 128 * 64 + 64 * 64 + 64 * 64) * 4; // 196608 B
    const int dec_sm = (69 * G4 + 128 * H + 128 * 64 + 5 * 64 +
                        64 * CSTR + 64 + 64 +
                        5 * 72 + 8 + 5 * 128 + 8) * 4;                             // ~159.5 KB
    const int net_smem = (enc_sm > dec_sm) ? enc_sm : dec_sm;
    cudaFuncSetAttribute(k_net, cudaFuncAttributeMaxDynamicSharedMemorySize, net_smem);

    const int repack_n = 192 * G4 + 69 * G4 + 128 * H;
    k_repack<<<(repack_n + 255) / 256, 256>>>(
        enc_Wih, enc_Whh, dec_Wih, dec_Whh, dec_attn_w1);
    k_net<<<B / TILE, NTHR, net_smem>>>(
        x, h0_enc, c0_enc, enc_bih, enc_bhh, enc_attn_w, dec_attn_w1,
        y_hist, h0_dec, c0_dec, dec_attn_b1, dec_attn_w2,
        dec_bih, dec_bhh, fc_w, fc_b, fcout_w, fcout_b, out);
}

// round 16
// speedup vs baseline: 1.2285x; 1.2285x over previous
#include <cuda_runtime.h>

typedef unsigned long long ull;

#define B 8192
#define L 10
#define D 128
#define H 64
#define G4 256          // 4*H
#define OUT 5
#define TILE 64
#define NTHR 512
#define QSTR 68
#define CSTR 68

// ------------------- global scratch -------------------
__device__ float g_xenc[(size_t)B * L * H];   // encoder hidden sequence
__device__ float g_pre[(size_t)B * L * H];    // x_enc @ W1x^T
__device__ float g_Wenc[192 * G4];            // [k][j*4+g]  k: 0..127 Wih, 128..191 Whh
__device__ float g_Wdec[69 * G4];             // [k][j*4+g]  k: 0..4 Wih, 5..68 Whh
__device__ float g_Wq[128 * H];               // [k][hh]     k: 0..63 W1h, 64..127 W1c

// ------------------- helpers -------------------
__device__ __forceinline__ ull pack2(float x, float y) {
    ull r; asm("mov.b64 %0, {%1, %2};" : "=l"(r) : "f"(x), "f"(y)); return r;
}
__device__ __forceinline__ ull dup2(float x) { return pack2(x, x); }
__device__ __forceinline__ float2 unpack2(ull v) {
    float2 f; asm("mov.b64 {%0, %1}, %2;" : "=f"(f.x), "=f"(f.y) : "l"(v)); return f;
}
__device__ __forceinline__ ull fma2(ull a, ull b, ull c) {
    ull d; asm("fma.rn.f32x2 %0, %1, %2, %3;" : "=l"(d) : "l"(a), "l"(b), "l"(c)); return d;
}
__device__ __forceinline__ float sigf(float x) {
    return __fdividef(1.f, 1.f + __expf(-x));
}
__device__ __forceinline__ float tanh_acc(float x) {
    return 1.f - __fdividef(2.f, __expf(2.f * x) + 1.f);
}
__device__ __forceinline__ float tanh_ap(float x) {
    float y; asm("tanh.approx.f32 %0, %1;" : "=f"(y) : "f"(x)); return y;
}

// =============================================================
// K0: repack weights
// =============================================================
__global__ void k_repack(const float* __restrict__ eWih, const float* __restrict__ eWhh,
                         const float* __restrict__ dWih, const float* __restrict__ dWhh,
                         const float* __restrict__ w1) {
    int idx = blockIdx.x * 256 + threadIdx.x;
    if (idx < 192 * G4) {
        int k = idx >> 8, c4 = idx & 255, j = c4 >> 2, g = c4 & 3;
        g_Wenc[idx] = (k < 128) ? eWih[(g * H + j) * D + k]
                                : eWhh[(g * H + j) * H + (k - 128)];
        return;
    }
    idx -= 192 * G4;
    if (idx < 69 * G4) {
        int k = idx >> 8, c4 = idx & 255, j = c4 >> 2, g = c4 & 3;
        g_Wdec[idx] = (k < 5) ? dWih[(g * H + j) * OUT + k]
                              : dWhh[(g * H + j) * H + (k - 5)];
        return;
    }
    idx -= 69 * G4;
    if (idx < 128 * H) {
        int k = idx >> 6, hh = idx & 63;
        g_Wq[idx] = (k < 64) ? w1[hh * 192 + k] : w1[hh * 192 + 64 + (k - 64)];
    }
}

// =============================================================
// K1: fused network, 512 threads/CTA, 64 rows/CTA.
// Encoder: Whh resident, Wih streamed, ping-pong h (no post-GEMM sync).
// Decoder: resident weights, ping-pong h (no F->G sync).
// =============================================================
__global__ __launch_bounds__(NTHR, 1) void k_net(
    const float* __restrict__ x, const float* __restrict__ h0,
    const float* __restrict__ c0, const float* __restrict__ bih,
    const float* __restrict__ bhh, const float* __restrict__ enc_attn_w,
    const float* __restrict__ w1,
    const float* __restrict__ y_hist, const float* __restrict__ h0d,
    const float* __restrict__ c0d,
    const float* __restrict__ dec_attn_b1, const float* __restrict__ dec_attn_w2,
    const float* __restrict__ dec_bih, const float* __restrict__ dec_bhh,
    const float* __restrict__ fc_w, const float* __restrict__ fc_b,
    const float* __restrict__ fcout_w, const float* __restrict__ fcout_b,
    float* __restrict__ out) {
    extern __shared__ float sm[];

    const int tid = threadIdx.x;
    const int rt = tid & 15, jc = tid >> 4;      // 16 row-threads x 32 col-threads
    const int r0 = rt * 4, j0 = jc * 2, jc8 = jc * 8;
    const int b0 = blockIdx.x * TILE;
    const int rowp = tid >> 3, dg = tid & 7;     // 64 rows x 8 d-groups

    // =========================================================
    // ENCODER — smem: Whh_s[64][256], Bs0/Bs1[32][256], Asx[128][64],
    //                 AshA/AshB[64][64], Ws1x[64][64]
    // =========================================================
    {
        float* Whh_s = sm;
        float* Bs0   = Whh_s + 64 * G4;
        float* Bs1   = Bs0 + 32 * G4;
        float* Asx   = Bs1 + 32 * G4;
        float* AshA  = Asx + 128 * 64;
        float* AshB  = AshA + 64 * 64;
        float* Ws1x  = AshB + 64 * 64;

        for (int i = tid; i < 64 * G4 / 4; i += NTHR)
            ((float4*)Whh_s)[i] = ((const float4*)(g_Wenc + 128 * G4))[i];
        for (int i = tid; i < 64 * 64; i += NTHR) {
            int e = i >> 6, hh = i & 63;
            Ws1x[e * 64 + hh] = w1[hh * 192 + 128 + e];
        }

        float4 at4[4];
        {
            float wx[L];
#pragma unroll
            for (int l = 0; l < L; l++) wx[l] = __ldg(enc_attn_w + 2 * H + l);
#pragma unroll
            for (int i = 0; i < 4; i++) at4[i] = make_float4(0.f, 0.f, 0.f, 0.f);
            const float* xp = x + (size_t)(b0 + rowp) * L * D + dg * 16;
#pragma unroll
            for (int l = 0; l < L; l++) {
#pragma unroll
                for (int i = 0; i < 4; i++) {
                    float4 v = *(const float4*)(xp + l * D + i * 4);
                    at4[i].x = fmaf(v.x, wx[l], at4[i].x);
                    at4[i].y = fmaf(v.y, wx[l], at4[i].y);
                    at4[i].z = fmaf(v.z, wx[l], at4[i].z);
                    at4[i].w = fmaf(v.w, wx[l], at4[i].w);
                }
            }
            float m = -1e30f;
#pragma unroll
            for (int i = 0; i < 4; i++)
                m = fmaxf(m, fmaxf(fmaxf(at4[i].x, at4[i].y), fmaxf(at4[i].z, at4[i].w)));
            m = fmaxf(m, __shfl_xor_sync(0xFFFFFFFFu, m, 1));
            m = fmaxf(m, __shfl_xor_sync(0xFFFFFFFFu, m, 2));
            m = fmaxf(m, __shfl_xor_sync(0xFFFFFFFFu, m, 4));
            float s = 0.f;
#pragma unroll
            for (int i = 0; i < 4; i++) {
                at4[i].x = __expf(at4[i].x - m); at4[i].y = __expf(at4[i].y - m);
                at4[i].z = __expf(at4[i].z - m); at4[i].w = __expf(at4[i].w - m);
                s += at4[i].x + at4[i].y + at4[i].z + at4[i].w;
            }
            s += __shfl_xor_sync(0xFFFFFFFFu, s, 1);
            s += __shfl_xor_sync(0xFFFFFFFFu, s, 2);
            s += __shfl_xor_sync(0xFFFFFFFFu, s, 4);
            float inv = __fdividef(1.f, s);
#pragma unroll
            for (int i = 0; i < 4; i++) {
                at4[i].x *= inv; at4[i].y *= inv; at4[i].z *= inv; at4[i].w *= inv;
            }
        }

        {   // h0 into AshA
            const float* hp = h0 + (size_t)(b0 + rowp) * H + dg * 8;
            float4 v0 = *(const float4*)(hp);
            float4 v1 = *(const float4*)(hp + 4);
            int j = dg * 8;
            AshA[(j + 0) * 64 + rowp] = v0.x; AshA[(j + 1) * 64 + rowp] = v0.y;
            AshA[(j + 2) * 64 + rowp] = v0.z; AshA[(j + 3) * 64 + rowp] = v0.w;
            AshA[(j + 4) * 64 + rowp] = v1.x; AshA[(j + 5) * 64 + rowp] = v1.y;
            AshA[(j + 6) * 64 + rowp] = v1.z; AshA[(j + 7) * 64 + rowp] = v1.w;
        }
        float cr0[4], cr1[4];
        ull bp[4];
#pragma unroll
        for (int p = 0; p < 4; p++) {
            int j = j0 + (p >> 1), g0 = (p & 1) * 2;
            bp[p] = pack2(bih[g0 * H + j] + bhh[g0 * H + j],
                          bih[(g0 + 1) * H + j] + bhh[(g0 + 1) * H + j]);
        }
#pragma unroll
        for (int i = 0; i < 4; i++) {
            cr0[i] = c0[(size_t)(b0 + r0 + i) * H + j0];
            cr1[i] = c0[(size_t)(b0 + r0 + i) * H + j0 + 1];
        }
        __syncthreads();

        for (int t = 0; t < L; t++) {
            float* hcur = (t & 1) ? AshB : AshA;
            float* hnxt = (t & 1) ? AshA : AshB;

            const float4* wp0 = (const float4*)g_Wenc + tid * 4;
            float4 f0 = wp0[0], f1 = wp0[1], f2 = wp0[2], f3 = wp0[3];

            {
                const float* xp = x + ((size_t)(b0 + rowp) * L + t) * D + dg * 16;
#pragma unroll
                for (int i = 0; i < 4; i++) {
                    float4 xv = *(const float4*)(xp + i * 4);
                    int k = dg * 16 + i * 4;
                    Asx[(k + 0) * 64 + rowp] = xv.x * at4[i].x;
                    Asx[(k + 1) * 64 + rowp] = xv.y * at4[i].y;
                    Asx[(k + 2) * 64 + rowp] = xv.z * at4[i].z;
                    Asx[(k + 3) * 64 + rowp] = xv.w * at4[i].w;
                }
            }
            {
                float4* b4 = (float4*)Bs0 + tid * 4;
                b4[0] = f0; b4[1] = f1; b4[2] = f2; b4[3] = f3;
            }
            __syncthreads();

            ull acc[4][4];
#pragma unroll
            for (int i = 0; i < 4; i++)
#pragma unroll
                for (int p = 0; p < 4; p++) acc[i][p] = bp[p];

            for (int kb = 0; kb < 4; kb++) {
                const float* Bsc = (kb & 1) ? Bs1 : Bs0;
                float4 n0, n1, n2, n3;
                if (kb < 3) {
                    const float4* wp = (const float4*)(g_Wenc + (kb + 1) * 32 * G4) + tid * 4;
                    n0 = wp[0]; n1 = wp[1]; n2 = wp[2]; n3 = wp[3];
                }
#pragma unroll
                for (int kk = 0; kk < 32; kk++) {
                    const float* ap = Asx + (kb * 32 + kk) * 64;
                    float4 a = *(const float4*)(ap + r0);
                    const ulonglong2* vp = (const ulonglong2*)(Bsc + kk * G4 + jc8);
                    ulonglong2 vA = vp[0], vB = vp[1];
                    float av[4] = {a.x, a.y, a.z, a.w};
#pragma unroll
                    for (int i = 0; i < 4; i++) {
                        ull ad = dup2(av[i]);
                        acc[i][0] = fma2(ad, vA.x, acc[i][0]);
                        acc[i][1] = fma2(ad, vA.y, acc[i][1]);
                        acc[i][2] = fma2(ad, vB.x, acc[i][2]);
                        acc[i][3] = fma2(ad, vB.y, acc[i][3]);
                    }
                }
                if (kb < 3) {
                    float* Bn = (kb & 1) ? Bs0 : Bs1;
                    float4* b4 = (float4*)Bn + tid * 4;
                    b4[0] = n0; b4[1] = n1; b4[2] = n2; b4[3] = n3;
                    __syncthreads();
                }
            }
            // recurrent part: += h @ Whh^T, resident; reads hcur
#pragma unroll 8
            for (int kk = 0; kk < 64; kk++) {
                float4 a = *(const float4*)(hcur + kk * 64 + r0);
                const ulonglong2* vp = (const ulonglong2*)(Whh_s + kk * G4 + jc8);
                ulonglong2 vA = vp[0], vB = vp[1];
                float av[4] = {a.x, a.y, a.z, a.w};
#pragma unroll
                for (int i = 0; i < 4; i++) {
                    ull ad = dup2(av[i]);
                    acc[i][0] = fma2(ad, vA.x, acc[i][0]);
                    acc[i][1] = fma2(ad, vA.y, acc[i][1]);
                    acc[i][2] = fma2(ad, vB.x, acc[i][2]);
                    acc[i][3] = fma2(ad, vB.y, acc[i][3]);
                }
            }
            // NO sync: activations write hnxt (different buffer); the "h
            // visible" sync below transitively orders laggard reads of hcur
            // before any writes to it at step t+1.

            // ---- activations (4 rows x 2 cols), write hnxt ----
#pragma unroll
            for (int i = 0; i < 4; i++) {
                float2 u0 = unpack2(acc[i][0]), u1 = unpack2(acc[i][1]);
                float2 u2 = unpack2(acc[i][2]), u3 = unpack2(acc[i][3]);
                float cn0 = sigf(u0.y) * cr0[i] + sigf(u0.x) * tanh_acc(u1.x);
                float hn0 = sigf(u1.y) * tanh_acc(cn0);
                float cn1 = sigf(u2.y) * cr1[i] + sigf(u2.x) * tanh_acc(u3.x);
                float hn1 = sigf(u3.y) * tanh_acc(cn1);
                cr0[i] = cn0; cr1[i] = cn1;
                hnxt[(j0) * 64 + r0 + i]     = hn0;
                hnxt[(j0 + 1) * 64 + r0 + i] = hn1;
                *(float2*)(g_xenc + ((size_t)(b0 + r0 + i) * L + t) * H + j0) =
                    make_float2(hn0, hn1);
            }
            __syncthreads();   // h visible

            // ---- fused pre-GEMM: pre = h @ W1x^T, reads hnxt ----
            {
                ull p0c0 = 0, p1c0 = 0, p0c1 = 0, p1c1 = 0;
#pragma unroll 8
                for (int e = 0; e < 64; e++) {
                    const float* hp = hnxt + e * 64;
                    ulonglong2 hA2 = *(const ulonglong2*)(hp + r0);
                    float2 w = *(const float2*)(Ws1x + e * 64 + j0);
                    ull w0 = dup2(w.x), w1d = dup2(w.y);
                    p0c0 = fma2(hA2.x, w0, p0c0);  p1c0 = fma2(hA2.y, w0, p1c0);
                    p0c1 = fma2(hA2.x, w1d, p0c1); p1c1 = fma2(hA2.y, w1d, p1c1);
                }
                float2 a0 = unpack2(p0c0), a1 = unpack2(p1c0);
                float2 c0v = unpack2(p0c1), c1v = unpack2(p1c1);
                float* pb = g_pre + ((size_t)(b0 + r0) * L + t) * H + j0;
                const size_t rs = (size_t)L * H;
                *(float2*)(pb + 0 * rs) = make_float2(a0.x, c0v.x);
                *(float2*)(pb + 1 * rs) = make_float2(a0.y, c0v.y);
                *(float2*)(pb + 2 * rs) = make_float2(a1.x, c1v.x);
                *(float2*)(pb + 3 * rs) = make_float2(a1.y, c1v.y);
            }
        }
    }
    __syncthreads();   // encoder smem dead; repartition for decoder

    // =========================================================
    // DECODER — resident weights, ping-pong h, 4 syncs/step
    // =========================================================
    {
        float* Wdec  = sm;                    // [69][256]
        float* Wq    = Wdec + 69 * G4;        // [128][64]
        float* hA    = Wq + 128 * H;          // [64][64]
        float* hB    = hA + 64 * 64;          // [64][64]
        float* Cc    = hB + 64 * 64;          // [64][64]
        float* As2   = Cc + 64 * 64;          // [5][64]
        float* q_s   = As2 + 5 * 64;          // [64][QSTR]
        float* ctx_s = q_s + 64 * QSTR;       // [64][CSTR]
        float* w2_s  = ctx_s + 64 * CSTR;     // [64]
        float* b1_s  = w2_s + 64;             // [64]
        float* fcw_s = b1_s + 64;             // [5][72]
        float* fcb_s = fcw_s + 5 * 72;        // [8]
        float* fow_s = fcb_s + 8;             // [5][128]
        float* fob_s = fow_s + 5 * 128;       // [8]

        const int rowq = tid >> 3, q8 = tid & 7;

        for (int i = tid; i < 69 * G4; i += NTHR)  Wdec[i] = g_Wdec[i];
        for (int i = tid; i < 128 * H; i += NTHR)  Wq[i]   = g_Wq[i];
        if (tid < 64) { w2_s[tid] = dec_attn_w2[tid]; b1_s[tid] = dec_attn_b1[tid]; }
        for (int i = tid; i < 5 * 69; i += NTHR) {
            int o = i / 69, k = i % 69;
            fcw_s[o * 72 + k] = fc_w[i];
        }
        for (int i = tid; i < 5 * 128; i += NTHR) fow_s[i] = fcout_w[i];
        if (tid < 5) { fcb_s[tid] = fc_b[tid]; fob_s[tid] = fcout_b[tid]; }

        {   // h0 -> hA, c0 -> Cc (transposed, 8 cols per thread)
            const float* hp = h0d + (size_t)(b0 + rowp) * H + dg * 8;
            const float* cp = c0d + (size_t)(b0 + rowp) * H + dg * 8;
            float4 h0v = *(const float4*)(hp), h1v = *(const float4*)(hp + 4);
            float4 c0v = *(const float4*)(cp), c1v = *(const float4*)(cp + 4);
            int j = dg * 8;
            hA[(j + 0) * 64 + rowp] = h0v.x; hA[(j + 1) * 64 + rowp] = h0v.y;
            hA[(j + 2) * 64 + rowp] = h0v.z; hA[(j + 3) * 64 + rowp] = h0v.w;
            hA[(j + 4) * 64 + rowp] = h1v.x; hA[(j + 5) * 64 + rowp] = h1v.y;
            hA[(j + 6) * 64 + rowp] = h1v.z; hA[(j + 7) * 64 + rowp] = h1v.w;
            Cc[(j + 0) * 64 + rowp] = c0v.x; Cc[(j + 1) * 64 + rowp] = c0v.y;
            Cc[(j + 2) * 64 + rowp] = c0v.z; Cc[(j + 3) * 64 + rowp] = c0v.w;
            Cc[(j + 4) * 64 + rowp] = c1v.x; Cc[(j + 5) * 64 + rowp] = c1v.y;
            Cc[(j + 6) * 64 + rowp] = c1v.z; Cc[(j + 7) * 64 + rowp] = c1v.w;
        }
        ull bp2[4];
#pragma unroll
        for (int p = 0; p < 4; p++) {
            int j = j0 + (p >> 1), g0 = (p & 1) * 2;
            bp2[p] = pack2(dec_bih[g0 * H + j] + dec_bhh[g0 * H + j],
                           dec_bih[(g0 + 1) * H + j] + dec_bhh[(g0 + 1) * H + j]);
        }
        __syncthreads();

        for (int t = 0; t < L; t++) {
            float* hcur = (t & 1) ? hB : hA;
            float* hnxt = (t & 1) ? hA : hB;

            // ---- Phase A: q = h @ W1h^T + c @ W1c^T + b1 (4 rows x 2 cols) ----
            {
                ull qa00 = 0, qa10 = 0, qa01 = 0, qa11 = 0;
#pragma unroll 4
                for (int k = 0; k < 64; k++) {
                    ulonglong2 hA2 = *(const ulonglong2*)(hcur + k * 64 + r0);
                    float2 w = *(const float2*)(Wq + k * H + j0);
                    ull w0 = dup2(w.x), w1d = dup2(w.y);
                    qa00 = fma2(hA2.x, w0, qa00);  qa10 = fma2(hA2.y, w0, qa10);
                    qa01 = fma2(hA2.x, w1d, qa01); qa11 = fma2(hA2.y, w1d, qa11);
                }
#pragma unroll 4
                for (int k = 0; k < 64; k++) {
                    ulonglong2 cA2 = *(const ulonglong2*)(Cc + k * 64 + r0);
                    float2 w = *(const float2*)(Wq + (64 + k) * H + j0);
                    ull w0 = dup2(w.x), w1d = dup2(w.y);
                    qa00 = fma2(cA2.x, w0, qa00);  qa10 = fma2(cA2.y, w0, qa10);
                    qa01 = fma2(cA2.x, w1d, qa01); qa11 = fma2(cA2.y, w1d, qa11);
                }
                float b1a = b1_s[j0], b1b = b1_s[j0 + 1];
                float2 u00 = unpack2(qa00), u10 = unpack2(qa10);
                float2 u01 = unpack2(qa01), u11 = unpack2(qa11);
                q_s[(r0 + 0) * QSTR + j0]     = u00.x + b1a;
                q_s[(r0 + 1) * QSTR + j0]     = u00.y + b1a;
                q_s[(r0 + 2) * QSTR + j0]     = u10.x + b1a;
                q_s[(r0 + 3) * QSTR + j0]     = u10.y + b1a;
                q_s[(r0 + 0) * QSTR + j0 + 1] = u01.x + b1b;
                q_s[(r0 + 1) * QSTR + j0 + 1] = u01.y + b1b;
                q_s[(r0 + 2) * QSTR + j0 + 1] = u11.x + b1b;
                q_s[(r0 + 3) * QSTR + j0 + 1] = u11.y + b1b;
            }
            __syncthreads();

            // ---- Phase B: scores -> softmax -> ctx (8 lanes per row) ----
            {
                float qv[8], w2v[8];
                const float* qrow = q_s + rowq * QSTR + q8 * 8;
                const float* w2p = w2_s + q8 * 8;
#pragma unroll
                for (int i = 0; i < 8; i++) { qv[i] = qrow[i]; w2v[i] = w2p[i]; }
                const float* prep = g_pre + (size_t)(b0 + rowq) * L * H + q8 * 8;
                float at[L];
#pragma unroll
                for (int l = 0; l < L; l++) {
                    float4 p0 = *(const float4*)(prep + l * H);
                    float4 p1 = *(const float4*)(prep + l * H + 4);
                    float s;
                    s = tanh_ap(p0.x + qv[0]) * w2v[0];
                    s = fmaf(tanh_ap(p0.y + qv[1]), w2v[1], s);
                    s = fmaf(tanh_ap(p0.z + qv[2]), w2v[2], s);
                    s = fmaf(tanh_ap(p0.w + qv[3]), w2v[3], s);
                    s = fmaf(tanh_ap(p1.x + qv[4]), w2v[4], s);
                    s = fmaf(tanh_ap(p1.y + qv[5]), w2v[5], s);
                    s = fmaf(tanh_ap(p1.z + qv[6]), w2v[6], s);
                    s = fmaf(tanh_ap(p1.w + qv[7]), w2v[7], s);
                    s += __shfl_xor_sync(0xFFFFFFFFu, s, 1);
                    s += __shfl_xor_sync(0xFFFFFFFFu, s, 2);
                    s += __shfl_xor_sync(0xFFFFFFFFu, s, 4);
                    at[l] = s;
                }
                float m = at[0];
#pragma unroll
                for (int l = 1; l < L; l++) m = fmaxf(m, at[l]);
                float ssum = 0.f;
#pragma unroll
                for (int l = 0; l < L; l++) { at[l] = __expf(at[l] - m); ssum += at[l]; }
                float inv = __fdividef(1.f, ssum);
#pragma unroll
                for (int l = 0; l < L; l++) at[l] *= inv;

                float4 c0a = make_float4(0.f, 0.f, 0.f, 0.f);
                float4 c1a = make_float4(0.f, 0.f, 0.f, 0.f);
                const float* xep = g_xenc + (size_t)(b0 + rowq) * L * H + q8 * 8;
#pragma unroll
                for (int l = 0; l < L; l++) {
                    float4 x0 = *(const float4*)(xep + l * H);
                    float4 x1 = *(const float4*)(xep + l * H + 4);
                    c0a.x = fmaf(at[l], x0.x, c0a.x); c0a.y = fmaf(at[l], x0.y, c0a.y);
                    c0a.z = fmaf(at[l], x0.z, c0a.z); c0a.w = fmaf(at[l], x0.w, c0a.w);
                    c1a.x = fmaf(at[l], x1.x, c1a.x); c1a.y = fmaf(at[l], x1.y, c1a.y);
                    c1a.z = fmaf(at[l], x1.z, c1a.z); c1a.w = fmaf(at[l], x1.w, c1a.w);
                }
                *(float4*)(ctx_s + rowq * CSTR + q8 * 8)     = c0a;
                *(float4*)(ctx_s + rowq * CSTR + q8 * 8 + 4) = c1a;
            }
            __syncthreads();

            // ---- Phase E: y_tilde = [ctx|y_t] @ fc_w^T + fc_b ----
            if (tid < 5 * 64) {
                int row = tid & 63, o = tid >> 6;
                float s = fcb_s[o];
                const float* fw = fcw_s + o * 72;
                const float* cx = ctx_s + row * CSTR;
#pragma unroll 8
                for (int k = 0; k < 64; k++) s = fmaf(fw[k], cx[k], s);
                const float* yh = y_hist + ((size_t)(b0 + row) * L + t) * OUT;
#pragma unroll
                for (int k = 0; k < OUT; k++) s = fmaf(fw[64 + k], yh[k], s);
                As2[o * 64 + row] = s;
            }
            __syncthreads();

            // ---- Phase F: gates (4 rows x 8 cols, k = 5 + 64) ----
            ull acc[4][4];
#pragma unroll
            for (int i = 0; i < 4; i++)
#pragma unroll
                for (int p = 0; p < 4; p++) acc[i][p] = bp2[p];
#pragma unroll
            for (int k = 0; k < 5; k++) {
                const float* ap = As2 + k * 64;
                float4 a = *(const float4*)(ap + r0);
                const ulonglong2* vp = (const ulonglong2*)(Wdec + k * G4 + jc8);
                ulonglong2 vA = vp[0], vB = vp[1];
                float av[4] = {a.x, a.y, a.z, a.w};
#pragma unroll
                for (int i = 0; i < 4; i++) {
                    ull ad = dup2(av[i]);
                    acc[i][0] = fma2(ad, vA.x, acc[i][0]);
                    acc[i][1] = fma2(ad, vA.y, acc[i][1]);
                    acc[i][2] = fma2(ad, vB.x, acc[i][2]);
                    acc[i][3] = fma2(ad, vB.y, acc[i][3]);
                }
            }
#pragma unroll 8
            for (int k = 0; k < 64; k++) {
                float4 a = *(const float4*)(hcur + k * 64 + r0);
                const ulonglong2* vp = (const ulonglong2*)(Wdec + (5 + k) * G4 + jc8);
                ulonglong2 vA = vp[0], vB = vp[1];
                float av[4] = {a.x, a.y, a.z, a.w};
#pragma unroll
                for (int i = 0; i < 4; i++) {
                    ull ad = dup2(av[i]);
                    acc[i][0] = fma2(ad, vA.x, acc[i][0]);
                    acc[i][1] = fma2(ad, vA.y, acc[i][1]);
                    acc[i][2] = fma2(ad, vB.x, acc[i][2]);
                    acc[i][3] = fma2(ad, vB.y, acc[i][3]);
                }
            }
            // NO sync: G writes hnxt (other buffer) + thread-private Cc cells.

            // ---- Phase G: LSTM cell, update h/c (4 rows x 2 cols) ----
#pragma unroll
            for (int i = 0; i < 4; i++) {
                float2 u0 = unpack2(acc[i][0]), u1 = unpack2(acc[i][1]);
                float2 u2 = unpack2(acc[i][2]), u3 = unpack2(acc[i][3]);
                float co0 = Cc[(j0) * 64 + r0 + i];
                float co1 = Cc[(j0 + 1) * 64 + r0 + i];
                float cn0 = sigf(u0.y) * co0 + sigf(u0.x) * tanh_acc(u1.x);
                float hn0 = sigf(u1.y) * tanh_acc(cn0);
                float cn1 = sigf(u2.y) * co1 + sigf(u2.x) * tanh_acc(u3.x);
                float hn1 = sigf(u3.y) * tanh_acc(cn1);
                hnxt[(j0) * 64 + r0 + i]     = hn0;
                hnxt[(j0 + 1) * 64 + r0 + i] = hn1;
                Cc[(j0) * 64 + r0 + i]       = cn0;
                Cc[(j0 + 1) * 64 + r0 + i]   = cn1;
            }
            __syncthreads();   // h/c visible for next step
        }

        // ---- out = [h | ctx] @ fcout_w^T + fcout_b  (final h in hA: L even) ----
        if (tid < 5 * 64) {
            int row = tid & 63, o = tid >> 6;
            float s = fob_s[o];
            const float* fw = fow_s + o * 128;
#pragma unroll 8
            for (int k = 0; k < 64; k++) s = fmaf(fw[k], hA[k * 64 + row], s);
            const float* cx = ctx_s + row * CSTR;
#pragma unroll 8
            for (int k = 0; k < 64; k++) s = fmaf(fw[64 + k], cx[k], s);
            out[(size_t)(b0 + row) * OUT + o] = s;
        }
    }
}

// =============================================================
// launcher
// =============================================================
extern "C" void kernel_launch(void* const* d_in, const int* in_sizes, int n_in,
                              void* d_out, int out_size) {
    const float* x           = (const float*)d_in[0];
    const float* y_hist      = (const float*)d_in[1];
    const float* h0_enc      = (const float*)d_in[2];
    const float* c0_enc      = (const float*)d_in[3];
    const float* h0_dec      = (const float*)d_in[4];
    const float* c0_dec      = (const float*)d_in[5];
    const float* enc_attn_w  = (const float*)d_in[6];
    // d_in[7] enc_attn_b: softmax-shift-invariant, unused
    const float* enc_Wih     = (const float*)d_in[8];
    const float* enc_Whh     = (const float*)d_in[9];
    const float* enc_bih     = (const float*)d_in[10];
    const float* enc_bhh     = (const float*)d_in[11];
    const float* dec_attn_w1 = (const float*)d_in[12];
    const float* dec_attn_b1 = (const float*)d_in[13];
    const float* dec_attn_w2 = (const float*)d_in[14];
    // d_in[15] dec_attn_b2: softmax-shift-invariant, unused
    const float* dec_Wih     = (const float*)d_in[16];
    const float* dec_Whh     = (const float*)d_in[17];
    const float* dec_bih     = (const float*)d_in[18];
    const float* dec_bhh     = (const float*)d_in[19];
    const float* fc_w        = (const float*)d_in[20];
    const float* fc_b        = (const float*)d_in[21];
    const float* fcout_w     = (const float*)d_in[22];
    const float* fcout_b     = (const float*)d_in[23];
    float* out = (float*)d_out;

    const int enc_sm = (64 * G4 + 2 * 32 * G4 + 128 * 64 + 2 * 64 * 64 + 64 * 64) * 4; // 212992 B
    const int dec_sm = (69 * G4 + 128 * H + 3 * 64 * 64 + 5 * 64 +
                        64 * QSTR + 64 * CSTR + 64 + 64 +
                        5 * 72 + 8 + 5 * 128 + 8) * 4;                                 // 193248 B
    const int net_smem = (enc_sm > dec_sm) ? enc_sm : dec_sm;
    cudaFuncSetAttribute(k_net, cudaFuncAttributeMaxDynamicSharedMemorySize, net_smem);

    const int repack_n = 192 * G4 + 69 * G4 + 128 * H;
    k_repack<<<(repack_n + 255) / 256, 256>>>(
        enc_Wih, enc_Whh, dec_Wih, dec_Whh, dec_attn_w1);
    k_net<<<B / TILE, NTHR, net_smem>>>(
        x, h0_enc, c0_enc, enc_bih, enc_bhh, enc_attn_w, dec_attn_w1,
        y_hist, h0_dec, c0_dec, dec_attn_b1, dec_attn_w2,
        dec_bih, dec_bhh, fc_w, fc_b, fcout_w, fcout_b, out);
}

// round 17
// speedup vs baseline: 1.3148x; 1.0702x over previous
#include <cuda_runtime.h>

typedef unsigned long long ull;

#define B 8192
#define L 10
#define D 128
#define H 64
#define G4 256          // 4*H
#define OUT 5
#define TILE 64
#define NTHR 512
#define QSTR 68
#define CSTR 68

// ------------------- global scratch -------------------
__device__ float g_xenc[(size_t)B * L * H];   // encoder hidden sequence
__device__ float g_pre[(size_t)B * L * H];    // x_enc @ W1x^T
__device__ float g_Wenc[192 * G4];            // [k][j*4+g]  k: 0..127 Wih, 128..191 Whh
__device__ float g_Wdec[69 * G4];             // [k][j*4+g]  k: 0..4 Wih, 5..68 Whh
__device__ float g_Wq[128 * H];               // [k][hh]     k: 0..63 W1h, 64..127 W1c

// ------------------- helpers -------------------
__device__ __forceinline__ ull pack2(float x, float y) {
    ull r; asm("mov.b64 %0, {%1, %2};" : "=l"(r) : "f"(x), "f"(y)); return r;
}
__device__ __forceinline__ ull dup2(float x) { return pack2(x, x); }
__device__ __forceinline__ float2 unpack2(ull v) {
    float2 f; asm("mov.b64 {%0, %1}, %2;" : "=f"(f.x), "=f"(f.y) : "l"(v)); return f;
}
__device__ __forceinline__ ull fma2(ull a, ull b, ull c) {
    ull d; asm("fma.rn.f32x2 %0, %1, %2, %3;" : "=l"(d) : "l"(a), "l"(b), "l"(c)); return d;
}
__device__ __forceinline__ float sigf(float x) {
    return __fdividef(1.f, 1.f + __expf(-x));
}
__device__ __forceinline__ float tanh_acc(float x) {
    return 1.f - __fdividef(2.f, __expf(2.f * x) + 1.f);
}
__device__ __forceinline__ float tanh_ap(float x) {
    float y; asm("tanh.approx.f32 %0, %1;" : "=f"(y) : "f"(x)); return y;
}
// cp.async 16B (global -> shared, L2-cached)
__device__ __forceinline__ void cpa16(unsigned dst, const void* src) {
    asm volatile("cp.async.cg.shared.global [%0], [%1], 16;" :: "r"(dst), "l"(src));
}
#define CPA_COMMIT() asm volatile("cp.async.commit_group;" ::: "memory")
#define CPA_WAIT0()  asm volatile("cp.async.wait_group 0;" ::: "memory")

// =============================================================
// K0: repack weights
// =============================================================
__global__ void k_repack(const float* __restrict__ eWih, const float* __restrict__ eWhh,
                         const float* __restrict__ dWih, const float* __restrict__ dWhh,
                         const float* __restrict__ w1) {
    int idx = blockIdx.x * 256 + threadIdx.x;
    if (idx < 192 * G4) {
        int k = idx >> 8, c4 = idx & 255, j = c4 >> 2, g = c4 & 3;
        g_Wenc[idx] = (k < 128) ? eWih[(g * H + j) * D + k]
                                : eWhh[(g * H + j) * H + (k - 128)];
        return;
    }
    idx -= 192 * G4;
    if (idx < 69 * G4) {
        int k = idx >> 8, c4 = idx & 255, j = c4 >> 2, g = c4 & 3;
        g_Wdec[idx] = (k < 5) ? dWih[(g * H + j) * OUT + k]
                              : dWhh[(g * H + j) * H + (k - 5)];
        return;
    }
    idx -= 69 * G4;
    if (idx < 128 * H) {
        int k = idx >> 6, hh = idx & 63;
        g_Wq[idx] = (k < 64) ? w1[hh * 192 + k] : w1[hh * 192 + 64 + (k - 64)];
    }
}

// =============================================================
// K1: fused network, 512 threads/CTA, 64 rows/CTA.
// Encoder: Whh resident; Wih streamed via cp.async (register-free).
// Decoder: verbatim measured-450us version.
// =============================================================
__global__ __launch_bounds__(NTHR, 1) void k_net(
    const float* __restrict__ x, const float* __restrict__ h0,
    const float* __restrict__ c0, const float* __restrict__ bih,
    const float* __restrict__ bhh, const float* __restrict__ enc_attn_w,
    const float* __restrict__ w1,
    const float* __restrict__ y_hist, const float* __restrict__ h0d,
    const float* __restrict__ c0d,
    const float* __restrict__ dec_attn_b1, const float* __restrict__ dec_attn_w2,
    const float* __restrict__ dec_bih, const float* __restrict__ dec_bhh,
    const float* __restrict__ fc_w, const float* __restrict__ fc_b,
    const float* __restrict__ fcout_w, const float* __restrict__ fcout_b,
    float* __restrict__ out) {
    extern __shared__ float sm[];

    const int tid = threadIdx.x;
    const int rt = tid & 15, jc = tid >> 4;      // 16 row-threads x 32 col-threads
    const int r0 = rt * 4, j0 = jc * 2, jc8 = jc * 8;
    const int b0 = blockIdx.x * TILE;
    const int rowp = tid >> 3, dg = tid & 7;     // 64 rows x 8 d-groups

    // =========================================================
    // ENCODER — smem: Whh_s[64][256], Bs0/Bs1[32][256], Asx[128][64],
    //                 Ash[64][64], Ws1x[64][64]
    // =========================================================
    {
        float* Whh_s = sm;
        float* Bs0   = Whh_s + 64 * G4;
        float* Bs1   = Bs0 + 32 * G4;
        float* Asx   = Bs1 + 32 * G4;
        float* Ash   = Asx + 128 * 64;
        float* Ws1x  = Ash + 64 * 64;

        // smem byte addresses for cp.async chunk staging (this thread's 64B slice)
        const unsigned bs0_a = (unsigned)__cvta_generic_to_shared(Bs0) + tid * 64;
        const unsigned bs1_a = (unsigned)__cvta_generic_to_shared(Bs1) + tid * 64;
        const char* wsrc = (const char*)g_Wenc + tid * 64;
        const int CHB = 32 * G4 * 4;   // chunk stride in bytes

        for (int i = tid; i < 64 * G4 / 4; i += NTHR)
            ((float4*)Whh_s)[i] = ((const float4*)(g_Wenc + 128 * G4))[i];
        for (int i = tid; i < 64 * 64; i += NTHR) {
            int e = i >> 6, hh = i & 63;
            Ws1x[e * 64 + hh] = w1[hh * 192 + 128 + e];
        }

        float4 at4[4];
        {
            float wx[L];
#pragma unroll
            for (int l = 0; l < L; l++) wx[l] = __ldg(enc_attn_w + 2 * H + l);
#pragma unroll
            for (int i = 0; i < 4; i++) at4[i] = make_float4(0.f, 0.f, 0.f, 0.f);
            const float* xp = x + (size_t)(b0 + rowp) * L * D + dg * 16;
#pragma unroll
            for (int l = 0; l < L; l++) {
#pragma unroll
                for (int i = 0; i < 4; i++) {
                    float4 v = *(const float4*)(xp + l * D + i * 4);
                    at4[i].x = fmaf(v.x, wx[l], at4[i].x);
                    at4[i].y = fmaf(v.y, wx[l], at4[i].y);
                    at4[i].z = fmaf(v.z, wx[l], at4[i].z);
                    at4[i].w = fmaf(v.w, wx[l], at4[i].w);
                }
            }
            float m = -1e30f;
#pragma unroll
            for (int i = 0; i < 4; i++)
                m = fmaxf(m, fmaxf(fmaxf(at4[i].x, at4[i].y), fmaxf(at4[i].z, at4[i].w)));
            m = fmaxf(m, __shfl_xor_sync(0xFFFFFFFFu, m, 1));
            m = fmaxf(m, __shfl_xor_sync(0xFFFFFFFFu, m, 2));
            m = fmaxf(m, __shfl_xor_sync(0xFFFFFFFFu, m, 4));
            float s = 0.f;
#pragma unroll
            for (int i = 0; i < 4; i++) {
                at4[i].x = __expf(at4[i].x - m); at4[i].y = __expf(at4[i].y - m);
                at4[i].z = __expf(at4[i].z - m); at4[i].w = __expf(at4[i].w - m);
                s += at4[i].x + at4[i].y + at4[i].z + at4[i].w;
            }
            s += __shfl_xor_sync(0xFFFFFFFFu, s, 1);
            s += __shfl_xor_sync(0xFFFFFFFFu, s, 2);
            s += __shfl_xor_sync(0xFFFFFFFFu, s, 4);
            float inv = __fdividef(1.f, s);
#pragma unroll
            for (int i = 0; i < 4; i++) {
                at4[i].x *= inv; at4[i].y *= inv; at4[i].z *= inv; at4[i].w *= inv;
            }
        }

        {
            const float* hp = h0 + (size_t)(b0 + rowp) * H + dg * 8;
            float4 v0 = *(const float4*)(hp);
            float4 v1 = *(const float4*)(hp + 4);
            int j = dg * 8;
            Ash[(j + 0) * 64 + rowp] = v0.x; Ash[(j + 1) * 64 + rowp] = v0.y;
            Ash[(j + 2) * 64 + rowp] = v0.z; Ash[(j + 3) * 64 + rowp] = v0.w;
            Ash[(j + 4) * 64 + rowp] = v1.x; Ash[(j + 5) * 64 + rowp] = v1.y;
            Ash[(j + 6) * 64 + rowp] = v1.z; Ash[(j + 7) * 64 + rowp] = v1.w;
        }
        float cr0[4], cr1[4];
        ull bp[4];
#pragma unroll
        for (int p = 0; p < 4; p++) {
            int j = j0 + (p >> 1), g0 = (p & 1) * 2;
            bp[p] = pack2(bih[g0 * H + j] + bhh[g0 * H + j],
                          bih[(g0 + 1) * H + j] + bhh[(g0 + 1) * H + j]);
        }
#pragma unroll
        for (int i = 0; i < 4; i++) {
            cr0[i] = c0[(size_t)(b0 + r0 + i) * H + j0];
            cr1[i] = c0[(size_t)(b0 + r0 + i) * H + j0 + 1];
        }
        __syncthreads();

        for (int t = 0; t < L; t++) {
            // issue chunk 0 -> Bs0 (register-free)
            cpa16(bs0_a,      wsrc);
            cpa16(bs0_a + 16, wsrc + 16);
            cpa16(bs0_a + 32, wsrc + 32);
            cpa16(bs0_a + 48, wsrc + 48);
            CPA_COMMIT();

            // stage wi = at*x_t transposed into Asx
            {
                const float* xp = x + ((size_t)(b0 + rowp) * L + t) * D + dg * 16;
#pragma unroll
                for (int i = 0; i < 4; i++) {
                    float4 xv = *(const float4*)(xp + i * 4);
                    int k = dg * 16 + i * 4;
                    Asx[(k + 0) * 64 + rowp] = xv.x * at4[i].x;
                    Asx[(k + 1) * 64 + rowp] = xv.y * at4[i].y;
                    Asx[(k + 2) * 64 + rowp] = xv.z * at4[i].z;
                    Asx[(k + 3) * 64 + rowp] = xv.w * at4[i].w;
                }
            }
            CPA_WAIT0();
            __syncthreads();   // Asx + Bs0 ready

            ull acc[4][4];
#pragma unroll
            for (int i = 0; i < 4; i++)
#pragma unroll
                for (int p = 0; p < 4; p++) acc[i][p] = bp[p];

            for (int kb = 0; kb < 4; kb++) {
                const float* Bsc = (kb & 1) ? Bs1 : Bs0;
                if (kb < 3) {   // issue next chunk into the other buffer
                    unsigned dst = (kb & 1) ? bs0_a : bs1_a;
                    const char* src = wsrc + (kb + 1) * CHB;
                    cpa16(dst,      src);
                    cpa16(dst + 16, src + 16);
                    cpa16(dst + 32, src + 32);
                    cpa16(dst + 48, src + 48);
                    CPA_COMMIT();
                }
#pragma unroll
                for (int kk = 0; kk < 32; kk++) {
                    const float* ap = Asx + (kb * 32 + kk) * 64;
                    float4 a = *(const float4*)(ap + r0);
                    const ulonglong2* vp = (const ulonglong2*)(Bsc + kk * G4 + jc8);
                    ulonglong2 vA = vp[0], vB = vp[1];
                    float av[4] = {a.x, a.y, a.z, a.w};
#pragma unroll
                    for (int i = 0; i < 4; i++) {
                        ull ad = dup2(av[i]);
                        acc[i][0] = fma2(ad, vA.x, acc[i][0]);
                        acc[i][1] = fma2(ad, vA.y, acc[i][1]);
                        acc[i][2] = fma2(ad, vB.x, acc[i][2]);
                        acc[i][3] = fma2(ad, vB.y, acc[i][3]);
                    }
                }
                if (kb < 3) {
                    CPA_WAIT0();
                    __syncthreads();   // next chunk landed; prior reads done
                }
            }
            // recurrent part: += h @ Whh^T, resident
#pragma unroll 8
            for (int kk = 0; kk < 64; kk++) {
                float4 a = *(const float4*)(Ash + kk * 64 + r0);
                const ulonglong2* vp = (const ulonglong2*)(Whh_s + kk * G4 + jc8);
                ulonglong2 vA = vp[0], vB = vp[1];
                float av[4] = {a.x, a.y, a.z, a.w};
#pragma unroll
                for (int i = 0; i < 4; i++) {
                    ull ad = dup2(av[i]);
                    acc[i][0] = fma2(ad, vA.x, acc[i][0]);
                    acc[i][1] = fma2(ad, vA.y, acc[i][1]);
                    acc[i][2] = fma2(ad, vB.x, acc[i][2]);
                    acc[i][3] = fma2(ad, vB.y, acc[i][3]);
                }
            }
            __syncthreads();   // Ash/Bs reads done before h overwrite

            // ---- activations (4 rows x 2 cols) ----
#pragma unroll
            for (int i = 0; i < 4; i++) {
                float2 u0 = unpack2(acc[i][0]), u1 = unpack2(acc[i][1]);
                float2 u2 = unpack2(acc[i][2]), u3 = unpack2(acc[i][3]);
                float cn0 = sigf(u0.y) * cr0[i] + sigf(u0.x) * tanh_acc(u1.x);
                float hn0 = sigf(u1.y) * tanh_acc(cn0);
                float cn1 = sigf(u2.y) * cr1[i] + sigf(u2.x) * tanh_acc(u3.x);
                float hn1 = sigf(u3.y) * tanh_acc(cn1);
                cr0[i] = cn0; cr1[i] = cn1;
                Ash[(j0) * 64 + r0 + i]     = hn0;
                Ash[(j0 + 1) * 64 + r0 + i] = hn1;
                *(float2*)(g_xenc + ((size_t)(b0 + r0 + i) * L + t) * H + j0) =
                    make_float2(hn0, hn1);
            }
            __syncthreads();   // h visible

            // ---- fused pre-GEMM: pre = h @ W1x^T (4 rows x 2 cols) ----
            {
                ull p0c0 = 0, p1c0 = 0, p0c1 = 0, p1c1 = 0;
#pragma unroll 8
                for (int e = 0; e < 64; e++) {
                    const float* hp = Ash + e * 64;
                    ulonglong2 hA = *(const ulonglong2*)(hp + r0);
                    float2 w = *(const float2*)(Ws1x + e * 64 + j0);
                    ull w0 = dup2(w.x), w1d = dup2(w.y);
                    p0c0 = fma2(hA.x, w0, p0c0);  p1c0 = fma2(hA.y, w0, p1c0);
                    p0c1 = fma2(hA.x, w1d, p0c1); p1c1 = fma2(hA.y, w1d, p1c1);
                }
                float2 a0 = unpack2(p0c0), a1 = unpack2(p1c0);
                float2 c0v = unpack2(p0c1), c1v = unpack2(p1c1);
                float* pb = g_pre + ((size_t)(b0 + r0) * L + t) * H + j0;
                const size_t rs = (size_t)L * H;
                *(float2*)(pb + 0 * rs) = make_float2(a0.x, c0v.x);
                *(float2*)(pb + 1 * rs) = make_float2(a0.y, c0v.y);
                *(float2*)(pb + 2 * rs) = make_float2(a1.x, c1v.x);
                *(float2*)(pb + 3 * rs) = make_float2(a1.y, c1v.y);
            }
            // next step stages Asx (disjoint from Ash); Ash overwrite guarded
            // by next step's post-GEMM sync.
        }
    }
    __syncthreads();   // encoder smem dead; repartition for decoder

    // =========================================================
    // DECODER PHASE (verbatim from the measured-450us kernel)
    // =========================================================
    {
        float* Wdec  = sm;                    // [69][256]
        float* Wq    = Wdec + 69 * G4;        // [128][64]
        float* Acs   = Wq + 128 * H;          // [128][64]: 0..63 h, 64..127 c
        float* As2   = Acs + 128 * 64;        // [5][64]
        float* q_s   = As2 + 5 * 64;          // [64][QSTR]
        float* ctx_s = q_s + 64 * QSTR;       // [64][CSTR]
        float* w2_s  = ctx_s + 64 * CSTR;     // [64]
        float* b1_s  = w2_s + 64;             // [64]
        float* fcw_s = b1_s + 64;             // [5][72]
        float* fcb_s = fcw_s + 5 * 72;        // [8]
        float* fow_s = fcb_s + 8;             // [5][128]
        float* fob_s = fow_s + 5 * 128;       // [8]

        const int rowq = tid >> 3, q8 = tid & 7;

        for (int i = tid; i < 69 * G4; i += NTHR)  Wdec[i] = g_Wdec[i];
        for (int i = tid; i < 128 * H; i += NTHR)  Wq[i]   = g_Wq[i];
        if (tid < 64) { w2_s[tid] = dec_attn_w2[tid]; b1_s[tid] = dec_attn_b1[tid]; }
        for (int i = tid; i < 5 * 69; i += NTHR) {
            int o = i / 69, k = i % 69;
            fcw_s[o * 72 + k] = fc_w[i];
        }
        for (int i = tid; i < 5 * 128; i += NTHR) fow_s[i] = fcout_w[i];
        if (tid < 5) { fcb_s[tid] = fc_b[tid]; fob_s[tid] = fcout_b[tid]; }

        {   // h0/c0 transposed (8 cols per thread)
            const float* hp = h0d + (size_t)(b0 + rowp) * H + dg * 8;
            const float* cp = c0d + (size_t)(b0 + rowp) * H + dg * 8;
            float4 h0v = *(const float4*)(hp), h1v = *(const float4*)(hp + 4);
            float4 c0v = *(const float4*)(cp), c1v = *(const float4*)(cp + 4);
            int j = dg * 8;
            Acs[(j + 0) * 64 + rowp] = h0v.x; Acs[(j + 1) * 64 + rowp] = h0v.y;
            Acs[(j + 2) * 64 + rowp] = h0v.z; Acs[(j + 3) * 64 + rowp] = h0v.w;
            Acs[(j + 4) * 64 + rowp] = h1v.x; Acs[(j + 5) * 64 + rowp] = h1v.y;
            Acs[(j + 6) * 64 + rowp] = h1v.z; Acs[(j + 7) * 64 + rowp] = h1v.w;
            Acs[(64 + j + 0) * 64 + rowp] = c0v.x; Acs[(64 + j + 1) * 64 + rowp] = c0v.y;
            Acs[(64 + j + 2) * 64 + rowp] = c0v.z; Acs[(64 + j + 3) * 64 + rowp] = c0v.w;
            Acs[(64 + j + 4) * 64 + rowp] = c1v.x; Acs[(64 + j + 5) * 64 + rowp] = c1v.y;
            Acs[(64 + j + 6) * 64 + rowp] = c1v.z; Acs[(64 + j + 7) * 64 + rowp] = c1v.w;
        }
        ull bp2[4];
#pragma unroll
        for (int p = 0; p < 4; p++) {
            int j = j0 + (p >> 1), g0 = (p & 1) * 2;
            bp2[p] = pack2(dec_bih[g0 * H + j] + dec_bhh[g0 * H + j],
                           dec_bih[(g0 + 1) * H + j] + dec_bhh[(g0 + 1) * H + j]);
        }
        __syncthreads();

        for (int t = 0; t < L; t++) {
            // ---- Phase A: q = [h|c] @ Wq + b1 (4 rows x 2 cols) ----
            {
                ull qa00 = 0, qa10 = 0, qa01 = 0, qa11 = 0;
#pragma unroll 4
                for (int k = 0; k < 128; k++) {
                    const float* ap = Acs + k * 64;
                    ulonglong2 hA = *(const ulonglong2*)(ap + r0);
                    float2 w = *(const float2*)(Wq + k * H + j0);
                    ull w0 = dup2(w.x), w1d = dup2(w.y);
                    qa00 = fma2(hA.x, w0, qa00);  qa10 = fma2(hA.y, w0, qa10);
                    qa01 = fma2(hA.x, w1d, qa01); qa11 = fma2(hA.y, w1d, qa11);
                }
                float b1a = b1_s[j0], b1b = b1_s[j0 + 1];
                float2 u00 = unpack2(qa00), u10 = unpack2(qa10);
                float2 u01 = unpack2(qa01), u11 = unpack2(qa11);
                q_s[(r0 + 0) * QSTR + j0]     = u00.x + b1a;
                q_s[(r0 + 1) * QSTR + j0]     = u00.y + b1a;
                q_s[(r0 + 2) * QSTR + j0]     = u10.x + b1a;
                q_s[(r0 + 3) * QSTR + j0]     = u10.y + b1a;
                q_s[(r0 + 0) * QSTR + j0 + 1] = u01.x + b1b;
                q_s[(r0 + 1) * QSTR + j0 + 1] = u01.y + b1b;
                q_s[(r0 + 2) * QSTR + j0 + 1] = u11.x + b1b;
                q_s[(r0 + 3) * QSTR + j0 + 1] = u11.y + b1b;
            }
            __syncthreads();

            // ---- Phase B: scores -> softmax -> ctx (8 lanes per row) ----
            {
                float qv[8], w2v[8];
                const float* qrow = q_s + rowq * QSTR + q8 * 8;
                const float* w2p = w2_s + q8 * 8;
#pragma unroll
                for (int i = 0; i < 8; i++) { qv[i] = qrow[i]; w2v[i] = w2p[i]; }
                const float* prep = g_pre + (size_t)(b0 + rowq) * L * H + q8 * 8;
                float at[L];
#pragma unroll
                for (int l = 0; l < L; l++) {
                    float4 p0 = *(const float4*)(prep + l * H);
                    float4 p1 = *(const float4*)(prep + l * H + 4);
                    float s;
                    s = tanh_ap(p0.x + qv[0]) * w2v[0];
                    s = fmaf(tanh_ap(p0.y + qv[1]), w2v[1], s);
                    s = fmaf(tanh_ap(p0.z + qv[2]), w2v[2], s);
                    s = fmaf(tanh_ap(p0.w + qv[3]), w2v[3], s);
                    s = fmaf(tanh_ap(p1.x + qv[4]), w2v[4], s);
                    s = fmaf(tanh_ap(p1.y + qv[5]), w2v[5], s);
                    s = fmaf(tanh_ap(p1.z + qv[6]), w2v[6], s);
                    s = fmaf(tanh_ap(p1.w + qv[7]), w2v[7], s);
                    s += __shfl_xor_sync(0xFFFFFFFFu, s, 1);
                    s += __shfl_xor_sync(0xFFFFFFFFu, s, 2);
                    s += __shfl_xor_sync(0xFFFFFFFFu, s, 4);
                    at[l] = s;
                }
                float m = at[0];
#pragma unroll
                for (int l = 1; l < L; l++) m = fmaxf(m, at[l]);
                float ssum = 0.f;
#pragma unroll
                for (int l = 0; l < L; l++) { at[l] = __expf(at[l] - m); ssum += at[l]; }
                float inv = __fdividef(1.f, ssum);
#pragma unroll
                for (int l = 0; l < L; l++) at[l] *= inv;

                float4 c0a = make_float4(0.f, 0.f, 0.f, 0.f);
                float4 c1a = make_float4(0.f, 0.f, 0.f, 0.f);
                const float* xep = g_xenc + (size_t)(b0 + rowq) * L * H + q8 * 8;
#pragma unroll
                for (int l = 0; l < L; l++) {
                    float4 x0 = *(const float4*)(xep + l * H);
                    float4 x1 = *(const float4*)(xep + l * H + 4);
                    c0a.x = fmaf(at[l], x0.x, c0a.x); c0a.y = fmaf(at[l], x0.y, c0a.y);
                    c0a.z = fmaf(at[l], x0.z, c0a.z); c0a.w = fmaf(at[l], x0.w, c0a.w);
                    c1a.x = fmaf(at[l], x1.x, c1a.x); c1a.y = fmaf(at[l], x1.y, c1a.y);
                    c1a.z = fmaf(at[l], x1.z, c1a.z); c1a.w = fmaf(at[l], x1.w, c1a.w);
                }
                *(float4*)(ctx_s + rowq * CSTR + q8 * 8)     = c0a;
                *(float4*)(ctx_s + rowq * CSTR + q8 * 8 + 4) = c1a;
            }
            __syncthreads();

            // ---- Phase E: y_tilde = [ctx|y_t] @ fc_w^T + fc_b ----
            if (tid < 5 * 64) {
                int row = tid & 63, o = tid >> 6;
                float s = fcb_s[o];
                const float* fw = fcw_s + o * 72;
                const float* cx = ctx_s + row * CSTR;
#pragma unroll 8
                for (int k = 0; k < 64; k++) s = fmaf(fw[k], cx[k], s);
                const float* yh = y_hist + ((size_t)(b0 + row) * L + t) * OUT;
#pragma unroll
                for (int k = 0; k < OUT; k++) s = fmaf(fw[64 + k], yh[k], s);
                As2[o * 64 + row] = s;
            }
            __syncthreads();

            // ---- Phase F: gates (4 rows x 8 cols, k = 5 + 64) ----
            ull acc[4][4];
#pragma unroll
            for (int i = 0; i < 4; i++)
#pragma unroll
                for (int p = 0; p < 4; p++) acc[i][p] = bp2[p];
#pragma unroll
            for (int k = 0; k < 5; k++) {
                const float* ap = As2 + k * 64;
                float4 a = *(const float4*)(ap + r0);
                const ulonglong2* vp = (const ulonglong2*)(Wdec + k * G4 + jc8);
                ulonglong2 vA = vp[0], vB = vp[1];
                float av[4] = {a.x, a.y, a.z, a.w};
#pragma unroll
                for (int i = 0; i < 4; i++) {
                    ull ad = dup2(av[i]);
                    acc[i][0] = fma2(ad, vA.x, acc[i][0]);
                    acc[i][1] = fma2(ad, vA.y, acc[i][1]);
                    acc[i][2] = fma2(ad, vB.x, acc[i][2]);
                    acc[i][3] = fma2(ad, vB.y, acc[i][3]);
                }
            }
#pragma unroll 8
            for (int k = 0; k < 64; k++) {
                const float* ap = Acs + k * 64;
                float4 a = *(const float4*)(ap + r0);
                const ulonglong2* vp = (const ulonglong2*)(Wdec + (5 + k) * G4 + jc8);
                ulonglong2 vA = vp[0], vB = vp[1];
                float av[4] = {a.x, a.y, a.z, a.w};
#pragma unroll
                for (int i = 0; i < 4; i++) {
                    ull ad = dup2(av[i]);
                    acc[i][0] = fma2(ad, vA.x, acc[i][0]);
                    acc[i][1] = fma2(ad, vA.y, acc[i][1]);
                    acc[i][2] = fma2(ad, vB.x, acc[i][2]);
                    acc[i][3] = fma2(ad, vB.y, acc[i][3]);
                }
            }
            __syncthreads();   // old-h reads done

            // ---- Phase G: LSTM cell, update h/c (4 rows x 2 cols) ----
#pragma unroll
            for (int i = 0; i < 4; i++) {
                float2 u0 = unpack2(acc[i][0]), u1 = unpack2(acc[i][1]);
                float2 u2 = unpack2(acc[i][2]), u3 = unpack2(acc[i][3]);
                float co0 = Acs[(64 + j0) * 64 + r0 + i];
                float co1 = Acs[(64 + j0 + 1) * 64 + r0 + i];
                float cn0 = sigf(u0.y) * co0 + sigf(u0.x) * tanh_acc(u1.x);
                float hn0 = sigf(u1.y) * tanh_acc(cn0);
                float cn1 = sigf(u2.y) * co1 + sigf(u2.x) * tanh_acc(u3.x);
                float hn1 = sigf(u3.y) * tanh_acc(cn1);
                Acs[(j0) * 64 + r0 + i]          = hn0;
                Acs[(j0 + 1) * 64 + r0 + i]      = hn1;
                Acs[(64 + j0) * 64 + r0 + i]     = cn0;
                Acs[(64 + j0 + 1) * 64 + r0 + i] = cn1;
            }
            __syncthreads();
        }

        // ---- out = [h | ctx] @ fcout_w^T + fcout_b ----
        if (tid < 5 * 64) {
            int row = tid & 63, o = tid >> 6;
            float s = fob_s[o];
            const float* fw = fow_s + o * 128;
#pragma unroll 8
            for (int k = 0; k < 64; k++) s = fmaf(fw[k], Acs[k * 64 + row], s);
            const float* cx = ctx_s + row * CSTR;
#pragma unroll 8
            for (int k = 0; k < 64; k++) s = fmaf(fw[64 + k], cx[k], s);
            out[(size_t)(b0 + row) * OUT + o] = s;
        }
    }
}

// =============================================================
// launcher
// =============================================================
extern "C" void kernel_launch(void* const* d_in, const int* in_sizes, int n_in,
                              void* d_out, int out_size) {
    const float* x           = (const float*)d_in[0];
    const float* y_hist      = (const float*)d_in[1];
    const float* h0_enc      = (const float*)d_in[2];
    const float* c0_enc      = (const float*)d_in[3];
    const float* h0_dec      = (const float*)d_in[4];
    const float* c0_dec      = (const float*)d_in[5];
    const float* enc_attn_w  = (const float*)d_in[6];
    // d_in[7] enc_attn_b: softmax-shift-invariant, unused
    const float* enc_Wih     = (const float*)d_in[8];
    const float* enc_Whh     = (const float*)d_in[9];
    const float* enc_bih     = (const float*)d_in[10];
    const float* enc_bhh     = (const float*)d_in[11];
    const float* dec_attn_w1 = (const float*)d_in[12];
    const float* dec_attn_b1 = (const float*)d_in[13];
    const float* dec_attn_w2 = (const float*)d_in[14];
    // d_in[15] dec_attn_b2: softmax-shift-invariant, unused
    const float* dec_Wih     = (const float*)d_in[16];
    const float* dec_Whh     = (const float*)d_in[17];
    const float* dec_bih     = (const float*)d_in[18];
    const float* dec_bhh     = (const float*)d_in[19];
    const float* fc_w        = (const float*)d_in[20];
    const float* fc_b        = (const float*)d_in[21];
    const float* fcout_w     = (const float*)d_in[22];
    const float* fcout_b     = (const float*)d_in[23];
    float* out = (float*)d_out;

    const int enc_sm = (64 * G4 + 2 * 32 * G4 + 128 * 64 + 64 * 64 + 64 * 64) * 4; // 196608 B
    const int dec_sm = (69 * G4 + 128 * H + 128 * 64 + 5 * 64 +
                        64 * QSTR + 64 * CSTR + 64 + 64 +
                        5 * 72 + 8 + 5 * 128 + 8) * 4;                             // 176864 B
    const int net_smem = (enc_sm > dec_sm) ? enc_sm : dec_sm;
    cudaFuncSetAttribute(k_net, cudaFuncAttributeMaxDynamicSharedMemorySize, net_smem);

    const int repack_n = 192 * G4 + 69 * G4 + 128 * H;
    k_repack<<<(repack_n + 255) / 256, 256>>>(
        enc_Wih, enc_Whh, dec_Wih, dec_Whh, dec_attn_w1);
    k_net<<<B / TILE, NTHR, net_smem>>>(
        x, h0_enc, c0_enc, enc_bih, enc_bhh, enc_attn_w, dec_attn_w1,
        y_hist, h0_dec, c0_dec, dec_attn_b1, dec_attn_w2,
        dec_bih, dec_bhh, fc_w, fc_b, fcout_w, fcout_b, out);
}